// round 16
// baseline (speedup 1.0000x reference)
#include <cuda_runtime.h>
#include <cuda_bf16.h>
#include <math.h>
#include <stdint.h>

// Problem constants
#define BB  2
#define SS  2048
#define HH  1024
#define NHD 16      // num heads
#define HDD 64      // head dim
#define RHH 4       // kv heads
#define MM  (BB*SS) // 4096 token rows
#define KW  (HH/2)  // 512 hi-words per row (bf16x2); merged row = 2*KW words

// word counts per tensor (hi-words, for merged split kernel)
#define XW  (MM*KW)
#define WQW (HH*KW)
#define WKW ((RHH*HDD)*KW)
#define TOTW (XW + WQW + 2*WKW + WQW)

// ---------------- scratch (static device memory; no allocs allowed) ----------
__device__ float    g_gates[MM];
__device__ int      g_order[MM];
__device__ uint32_t g_x [(size_t)MM * 2 * KW];          // x merged hi/lo interleaved
__device__ uint32_t g_wq[(size_t)HH * 2 * KW];
__device__ uint32_t g_wk[(size_t)(RHH*HDD) * 2 * KW];
__device__ uint32_t g_wv[(size_t)(RHH*HDD) * 2 * KW];
__device__ uint32_t g_wo[(size_t)HH * 2 * KW];
__device__ uint32_t g_qph[(size_t)MM * 512];            // Q row-packed bf16 hi (raw order)
__device__ uint32_t g_qpl[(size_t)MM * 512];
__device__ uint32_t g_kp [(size_t)RHH * MM * 64];       // K frag-packed (hi+lo interleaved u4)
__device__ uint4    g_vp [(size_t)BB * RHH * HDD * 512];// V transposed frag-packed
__device__ uint32_t g_o  [(size_t)MM * 1024];           // attn out merged hi/lo interleaved

// ---------------- bf16 helpers ----------------------------------------------
__device__ __forceinline__ uint32_t pack_bf16(float lowElem, float highElem) {
    uint32_t r;
    asm("cvt.rn.bf16x2.f32 %0, %1, %2;" : "=r"(r) : "f"(highElem), "f"(lowElem));
    return r;
}
__device__ __forceinline__ float bf16_round(float x) {
    return __bfloat162float(__float2bfloat16(x));
}
__device__ __forceinline__ void bf16_split2(float a, float b, uint32_t& hi, uint32_t& lo) {
    hi = pack_bf16(a, b);
    lo = pack_bf16(a - bf16_round(a), b - bf16_round(b));
}
__device__ __forceinline__ void mma_bf16(float* c, uint32_t a0, uint32_t a1, uint32_t a2,
                                         uint32_t a3, uint32_t b0, uint32_t b1) {
    asm volatile(
        "mma.sync.aligned.m16n8k16.row.col.f32.bf16.bf16.f32 "
        "{%0,%1,%2,%3}, {%4,%5,%6,%7}, {%8,%9}, {%0,%1,%2,%3};"
        : "+f"(c[0]), "+f"(c[1]), "+f"(c[2]), "+f"(c[3])
        : "r"(a0), "r"(a1), "r"(a2), "r"(a3), "r"(b0), "r"(b1));
}
__device__ __forceinline__ uint32_t smem_u32(const void* p) {
    uint32_t a;
    asm("{ .reg .u64 t; cvta.to.shared.u64 t, %1; cvt.u32.u64 %0, t; }" : "=r"(a) : "l"(p));
    return a;
}
__device__ __forceinline__ void cpa16(uint32_t dst, const void* src) {
    asm volatile("cp.async.ca.shared.global [%0], [%1], 16;" :: "r"(dst), "l"(src));
}
#define CPA_COMMIT() asm volatile("cp.async.commit_group;" ::: "memory")
#define CPA_WAIT(n)  asm volatile("cp.async.wait_group %0;" :: "n"(n) : "memory")

// ---------------- merged fp32 -> interleaved hi/lo split ---------------------
__global__ __launch_bounds__(256)
void split_all(const float* __restrict__ x,  const float* __restrict__ Wq,
               const float* __restrict__ Wk, const float* __restrict__ Wv,
               const float* __restrict__ Wo,
               uint32_t* __restrict__ xo,  uint32_t* __restrict__ wqo,
               uint32_t* __restrict__ wko, uint32_t* __restrict__ wvo,
               uint32_t* __restrict__ woo) {
    for (int i = blockIdx.x * 256 + threadIdx.x; i < TOTW; i += gridDim.x * 256) {
        const float* src; uint32_t* dst; int local;
        if (i < XW)                      { src = x;  dst = xo;  local = i; }
        else if (i < XW + WQW)           { src = Wq; dst = wqo; local = i - XW; }
        else if (i < XW + WQW + WKW)     { src = Wk; dst = wko; local = i - XW - WQW; }
        else if (i < XW + WQW + 2*WKW)   { src = Wv; dst = wvo; local = i - XW - WQW - WKW; }
        else                             { src = Wo; dst = woo; local = i - XW - WQW - 2*WKW; }
        float2 v = *(const float2*)(src + 2 * (size_t)local);
        uint32_t h, l;
        bf16_split2(v.x, v.y, h, l);
        int t = local & 7;
        size_t pos = ((size_t)(local >> 3)) * 16 + (t & 3) * 4 + (t >> 2);
        dst[pos] = h; dst[pos + 2] = l;
    }
}

// ==================== tensor-core bf16x3 GEMM (merged interleaved) ===========
#define PWG 48
#define STGW (2 * 128 * PWG)
#define GM_SMEM (2 * STGW * 4)

__device__ __forceinline__ void gemm_body(const uint32_t* __restrict__ A,
                                          const uint32_t* __restrict__ B,
                                          float* __restrict__ C,
                                          uint32_t* __restrict__ outh,
                                          uint32_t* __restrict__ outl,
                                          uint4* __restrict__ vpout,
                                          int N, int Kw, int mode,
                                          int rowBase, int colBase, uint32_t* sm) {
    int tid = threadIdx.x, lane = tid & 31, wid = tid >> 5;
    int gid = lane >> 2, tig = lane & 3;
    int wM = wid >> 1, wN = wid & 1;
    uint32_t smb = smem_u32(sm);

    int lrow = tid >> 1, lh16 = (tid & 1) * 16;
    const uint32_t* pA = A + (size_t)(rowBase + lrow) * (2 * Kw) + lh16;
    const uint32_t* pB = B + (size_t)(colBase + lrow) * (2 * Kw) + lh16;
    uint32_t dstOff = (lrow * PWG + lh16) * 4;

    float acc[2][8][4];
#pragma unroll
    for (int mt = 0; mt < 2; mt++)
#pragma unroll
        for (int nt = 0; nt < 8; nt++)
#pragma unroll
            for (int c = 0; c < 4; c++) acc[mt][nt][c] = 0.f;

    const int NST = Kw / 16;

    {
        uint32_t dA = smb + dstOff;
        uint32_t dB = dA + 128 * PWG * 4;
#pragma unroll
        for (int c = 0; c < 4; c++) { cpa16(dA + c * 16, pA + c * 4); cpa16(dB + c * 16, pB + c * 4); }
        CPA_COMMIT();
    }

    for (int s = 0; s < NST; s++) {
        int buf = s & 1;
        if (s + 1 < NST) {
            int off = (s + 1) * 32;
            uint32_t dA = smb + (buf ^ 1) * STGW * 4 + dstOff;
            uint32_t dB = dA + 128 * PWG * 4;
#pragma unroll
            for (int c = 0; c < 4; c++) {
                cpa16(dA + c * 16, pA + off + c * 4);
                cpa16(dB + c * 16, pB + off + c * 4);
            }
            CPA_COMMIT();
            CPA_WAIT(1);
        } else {
            CPA_WAIT(0);
        }
        __syncthreads();

        uint32_t* sA = sm + buf * STGW;
        uint32_t* sB = sA + 128 * PWG;

#pragma unroll
        for (int ks = 0; ks < 2; ks++) {
            uint32_t ah[2][4], al[2][4];
#pragma unroll
            for (int mt = 0; mt < 2; mt++) {
                int r0 = (wM * 32 + mt * 16 + gid) * PWG + ks * 16 + tig * 4;
                uint4 q1 = *(const uint4*)(sA + r0);
                uint4 q2 = *(const uint4*)(sA + r0 + 8 * PWG);
                ah[mt][0] = q1.x; ah[mt][1] = q2.x; ah[mt][2] = q1.y; ah[mt][3] = q2.y;
                al[mt][0] = q1.z; al[mt][1] = q2.z; al[mt][2] = q1.w; al[mt][3] = q2.w;
            }
#pragma unroll
            for (int nt = 0; nt < 8; nt++) {
                int n0 = (wN * 64 + nt * 8 + gid) * PWG + ks * 16 + tig * 4;
                uint4 qb = *(const uint4*)(sB + n0);
#pragma unroll
                for (int mt = 0; mt < 2; mt++) {
                    mma_bf16(acc[mt][nt], ah[mt][0], ah[mt][1], ah[mt][2], ah[mt][3], qb.x, qb.y);
                    mma_bf16(acc[mt][nt], ah[mt][0], ah[mt][1], ah[mt][2], ah[mt][3], qb.z, qb.w);
                    mma_bf16(acc[mt][nt], al[mt][0], al[mt][1], al[mt][2], al[mt][3], qb.x, qb.y);
                }
            }
        }
        __syncthreads();
    }

    // ---------------- epilogue ----------------
    if (mode == 0) {
#pragma unroll
        for (int mt = 0; mt < 2; mt++) {
            int r0 = rowBase + wM * 32 + mt * 16 + gid;
#pragma unroll
            for (int nt = 0; nt < 8; nt++) {
                int c0 = colBase + wN * 64 + nt * 8 + 2 * tig;
                *(float2*)(C + (size_t)r0 * N + c0) = make_float2(acc[mt][nt][0], acc[mt][nt][1]);
                *(float2*)(C + (size_t)(r0 + 8) * N + c0) = make_float2(acc[mt][nt][2], acc[mt][nt][3]);
            }
        }
    } else if (mode == 1) {   // Q row-packed raw order, scaled 1/8
#pragma unroll
        for (int mt = 0; mt < 2; mt++) {
            int r0 = rowBase + wM * 32 + mt * 16 + gid;
#pragma unroll
            for (int nt = 0; nt < 8; nt++) {
                int c0 = colBase + wN * 64 + nt * 8 + 2 * tig;
                int hh = c0 >> 6, w32 = (c0 & 63) >> 1;
                uint32_t h0, l0, h1, l1;
                bf16_split2(acc[mt][nt][0] * 0.125f, acc[mt][nt][1] * 0.125f, h0, l0);
                bf16_split2(acc[mt][nt][2] * 0.125f, acc[mt][nt][3] * 0.125f, h1, l1);
                size_t i0 = ((size_t)r0 * 16 + hh) * 32 + w32;
                size_t i1 = ((size_t)(r0 + 8) * 16 + hh) * 32 + w32;
                outh[i0] = h0; outl[i0] = l0;
                outh[i1] = h1; outl[i1] = l1;
            }
        }
    } else if (mode == 2) {   // K frag-packed interleaved
#pragma unroll
        for (int mt = 0; mt < 2; mt++) {
            int r0 = rowBase + wM * 32 + mt * 16 + gid;
#pragma unroll
            for (int nt = 0; nt < 8; nt++) {
                int c0 = colBase + wN * 64 + nt * 8 + 2 * tig;
                int kvh = c0 >> 6, wl = (c0 & 63) >> 1;
                int ks = wl >> 3, tigg = wl & 7;
                int tA = tigg & 3, comp = (tigg & 4) ? 1 : 0;
                size_t wi0 = (((size_t)kvh * MM + r0) * 16 + ks * 4 + tA) * 4;
                size_t wi1 = wi0 + 8 * 16 * 4;
                uint32_t h0, l0, h1, l1;
                bf16_split2(acc[mt][nt][0], acc[mt][nt][1], h0, l0);
                bf16_split2(acc[mt][nt][2], acc[mt][nt][3], h1, l1);
                outh[wi0 + comp] = h0; outh[wi0 + comp + 2] = l0;
                outh[wi1 + comp] = h1; outh[wi1 + comp + 2] = l1;
            }
        }
    } else {                  // mode 3: V transposed frag-packed (shfl pair exchange)
#pragma unroll
        for (int mt = 0; mt < 2; mt++) {
            int r = wM * 32 + mt * 16 + gid;
            int tok = rowBase + r;
            int b = tok / SS;
            int j64 = tok % SS;
            int kb = j64 >> 6;
            int j = j64 & 63;
            int ks = j >> 4, tg = (j >> 1) & 3;
            bool even = (gid & 1) == 0;
#pragma unroll
            for (int nt = 0; nt < 8; nt++) {
                int c0 = colBase + wN * 64 + nt * 8 + 2 * tig;
                float p0 = __shfl_xor_sync(0xffffffffu, acc[mt][nt][0], 4);
                float p1 = __shfl_xor_sync(0xffffffffu, acc[mt][nt][1], 4);
                float p2 = __shfl_xor_sync(0xffffffffu, acc[mt][nt][2], 4);
                float p3 = __shfl_xor_sync(0xffffffffu, acc[mt][nt][3], 4);
                float v0, v1, v2, v3; int d;
                if (even) { d = c0;     v0 = acc[mt][nt][0]; v1 = p0; v2 = acc[mt][nt][2]; v3 = p2; }
                else      { d = c0 + 1; v0 = p1; v1 = acc[mt][nt][1]; v2 = p3; v3 = acc[mt][nt][3]; }
                int kvh = d >> 6, dd = d & 63;
                uint32_t hx, lx, hy, ly;
                bf16_split2(v0, v1, hx, lx);
                bf16_split2(v2, v3, hy, ly);
                vpout[((size_t)(b * RHH + kvh) * 64 + dd) * 512 + kb * 16 + ks * 4 + tg] =
                    make_uint4(hx, hy, lx, ly);
            }
        }
    }
}

// fused Q+K+V projection in one launch (wave packing)
__global__ __launch_bounds__(256, 2)
void gemm_qkv(const uint32_t* __restrict__ xm,  const uint32_t* __restrict__ wqm,
              const uint32_t* __restrict__ wkm, const uint32_t* __restrict__ wvm,
              uint32_t* __restrict__ qh, uint32_t* __restrict__ ql,
              uint32_t* __restrict__ kp, uint4* __restrict__ vpout) {
    extern __shared__ uint32_t smg[];
    int bx = blockIdx.x;
    if (bx < 256) {
        gemm_body(xm, wqm, nullptr, qh, ql, nullptr, HH, KW, 1,
                  (bx >> 3) * 128, (bx & 7) * 128, smg);
    } else if (bx < 320) {
        int c = bx - 256;
        gemm_body(xm, wkm, nullptr, kp, nullptr, nullptr, RHH * HDD, KW, 2,
                  (c >> 1) * 128, (c & 1) * 128, smg);
    } else {
        int c = bx - 320;
        gemm_body(xm, wvm, nullptr, nullptr, nullptr, vpout, RHH * HDD, KW, 3,
                  (c >> 1) * 128, (c & 1) * 128, smg);
    }
}

__global__ __launch_bounds__(256, 2)
void gemm_mma(const uint32_t* __restrict__ A, const uint32_t* __restrict__ B,
              float* __restrict__ C, uint32_t* __restrict__ outh,
              uint32_t* __restrict__ outl, int N, int Kw, int mode) {
    extern __shared__ uint32_t smg[];
    gemm_body(A, B, C, outh, outl, nullptr, N, Kw, mode,
              blockIdx.y * 128, blockIdx.x * 128, smg);
}

// ---------------- build compacted row order: [causal asc | local asc] --------
__global__ __launch_bounds__(256)
void build_order(const float* __restrict__ gates, int* __restrict__ order) {
    int b = blockIdx.x, tid = threadIdx.x;
    __shared__ int cnt[256];
    bool loc[8];
    int c = 0;
#pragma unroll
    for (int i = 0; i < 8; i++) {
        loc[i] = gates[b * SS + tid * 8 + i] <= 0.5f;
        if (!loc[i]) c++;
    }
    cnt[tid] = c;
    __syncthreads();
    for (int off = 1; off < 256; off <<= 1) {
        int add = (tid >= off) ? cnt[tid - off] : 0;
        __syncthreads();
        cnt[tid] += add;
        __syncthreads();
    }
    int nC = cnt[255];
    int cb = cnt[tid] - c;
    int lb = nC + (tid * 8 - cb);
#pragma unroll
    for (int i = 0; i < 8; i++) {
        if (loc[i]) order[b * SS + lb++] = tid * 8 + i;
        else        order[b * SS + cb++] = tid * 8 + i;
    }
}

// ==================== mma flash attention (compacted rows) ===================
#define AT_SMEM (5888 * 16)

__global__ __launch_bounds__(256, 2)
void attn_mma(const uint32_t* __restrict__ qph, const uint32_t* __restrict__ qpl,
              const uint4* __restrict__ kp,  const uint4* __restrict__ vp,
              const float* __restrict__ gates, const int* __restrict__ order,
              uint32_t* __restrict__ go) {
    extern __shared__ uint4 sm4[];
    __shared__ int srows[128];
    __shared__ int sminlo, smaxhi;
    uint32_t smb = smem_u32(sm4);
    uint32_t* sQw = (uint32_t*)sm4;

    int bx = blockIdx.x;
    int t = (bx < 8) ? (7 - bx) : bx;   // longest (causal) tiles first
    int h = blockIdx.y, b = blockIdx.z;
    int tid = threadIdx.x, lane = tid & 31, w = tid >> 5;
    int gid = lane >> 2, tig = lane & 3;
    int kvh = h & 3;

    if (tid == 0) { sminlo = SS; smaxhi = 0; }
    if (tid < 128) srows[tid] = order[b * SS + t * 128 + tid];
    __syncthreads();
    if (tid < 128) {
        int myi = srows[tid];
        bool isl = gates[b * SS + myi] <= 0.5f;
        int lo = isl ? max(0, myi - 64) : 0;
        int hi = isl ? min(SS - 1, myi + 64) : myi;
        atomicMin(&sminlo, lo);
        atomicMax(&smaxhi, hi);
    }

    // ---- Q gather: row-major packed (raw order) -> frag layout ----
    {
        int r = tid >> 1, half = tid & 1;
        int ri = srows[r];
        const uint32_t* src = (half ? qpl : qph) + ((size_t)(b * SS + ri) * 16 + h) * 32;
        uint32_t* dst = sQw + half * 4096;
        int wd = r >> 4, g2 = r & 15;
        int gidq = g2 & 7, hiRow = g2 >> 3;
#pragma unroll
        for (int w32 = 0; w32 < 32; w32++) {
            int ks = w32 >> 3, rem = w32 & 7;
            int tg2 = rem & 3, comp = ((rem >> 2) << 1) | hiRow;
            dst[(((wd * 8 + gidq) * 4 + ks) * 4 + tg2) * 4 + comp] = src[w32];
        }
    }
    __syncthreads();

    int kbStart = sminlo >> 6;
    int kbEnd = (smaxhi >> 6) + 1;

    int i0 = srows[w * 16 + gid], i1 = srows[w * 16 + gid + 8];
    bool isl0 = gates[b * SS + i0] <= 0.5f;
    bool isl1 = gates[b * SS + i1] <= 0.5f;

    float m0 = -1e30f, m1 = -1e30f, l0s = 0.f, l1s = 0.f;
    float o[8][4];
#pragma unroll
    for (int nt = 0; nt < 8; nt++)
#pragma unroll
        for (int c = 0; c < 4; c++) o[nt][c] = 0.f;

    const uint4* kbase = kp + ((size_t)kvh * MM + b * SS) * 16;
    const uint4* vbase = vp + (size_t)(b * RHH + kvh) * 64 * 512;
    int fj = tid >> 2, fq = (tid & 3) * 4;

    // prologue: K[kbStart] group, then V[kbStart] group (separate commits)
    {
        const uint4* gk = kbase + ((size_t)(kbStart * 64 + fj)) * 16 + fq;
        uint32_t dk = smb + (2048 + fj * 20 + fq) * 16;
#pragma unroll
        for (int c = 0; c < 4; c++) cpa16(dk + c * 16, gk + c);
        CPA_COMMIT();
        const uint4* gv = vbase + (size_t)fj * 512 + kbStart * 16 + fq;
        uint32_t dv = smb + (4608 + fj * 20 + fq) * 16;
#pragma unroll
        for (int c = 0; c < 4; c++) cpa16(dv + c * 16, gv + c);
        CPA_COMMIT();
    }

    for (int kb = kbStart; kb < kbEnd; kb++) {
        int buf = (kb - kbStart) & 1;
        // invariant at top: outstanding groups = {K[kb], V[kb]} (K older)
        CPA_WAIT(1);          // K[kb] complete; V[kb] may still be in flight
        __syncthreads();

        if (kb + 1 < kbEnd) { // issue next K early; overlaps whole iteration
            const uint4* gk = kbase + ((size_t)((kb + 1) * 64 + fj)) * 16 + fq;
            uint32_t dk = smb + (2048 + (buf ^ 1) * 1280 + fj * 20 + fq) * 16;
#pragma unroll
            for (int c = 0; c < 4; c++) cpa16(dk + c * 16, gk + c);
            CPA_COMMIT();
        }

        const uint4* sK = sm4 + 2048 + buf * 1280;
        const uint4* sV = sm4 + 4608;

        // ---- QK^T (V[kb] load overlaps this) ----
        float s[8][4];
#pragma unroll
        for (int nt = 0; nt < 8; nt++)
#pragma unroll
            for (int c = 0; c < 4; c++) s[nt][c] = 0.f;

#pragma unroll
        for (int ks = 0; ks < 4; ks++) {
            uint4 qh = sm4[w * 128 + gid * 16 + ks * 4 + tig];
            uint4 ql = sm4[1024 + w * 128 + gid * 16 + ks * 4 + tig];
#pragma unroll
            for (int nt = 0; nt < 8; nt++) {
                uint4 kk = sK[(nt * 8 + gid) * 20 + ks * 4 + tig];
                mma_bf16(s[nt], qh.x, qh.y, qh.z, qh.w, kk.x, kk.y);
                mma_bf16(s[nt], qh.x, qh.y, qh.z, qh.w, kk.z, kk.w);
                mma_bf16(s[nt], ql.x, ql.y, ql.z, ql.w, kk.x, kk.y);
            }
        }

        // ---- mask + online softmax (clamp-free; masked-only blocks self-correct) ----
        float rm0 = -1e30f, rm1 = -1e30f;
#pragma unroll
        for (int nt = 0; nt < 8; nt++) {
            int jb = kb * 64 + nt * 8 + 2 * tig;
#pragma unroll
            for (int c = 0; c < 2; c++) {
                int j = jb + c;
                bool v0 = isl0 ? (abs(i0 - j) <= 64) : (j <= i0);
                s[nt][c] = v0 ? s[nt][c] : -1e30f;
                rm0 = fmaxf(rm0, s[nt][c]);
                bool v1 = isl1 ? (abs(i1 - j) <= 64) : (j <= i1);
                s[nt][2 + c] = v1 ? s[nt][2 + c] : -1e30f;
                rm1 = fmaxf(rm1, s[nt][2 + c]);
            }
        }
        rm0 = fmaxf(rm0, __shfl_xor_sync(0xffffffffu, rm0, 1));
        rm0 = fmaxf(rm0, __shfl_xor_sync(0xffffffffu, rm0, 2));
        rm1 = fmaxf(rm1, __shfl_xor_sync(0xffffffffu, rm1, 1));
        rm1 = fmaxf(rm1, __shfl_xor_sync(0xffffffffu, rm1, 2));

        float mn0 = fmaxf(m0, rm0), mn1 = fmaxf(m1, rm1);
        float al0f = __expf(m0 - mn0);
        float al1f = __expf(m1 - mn1);
        float rs0 = 0.f, rs1 = 0.f;
#pragma unroll
        for (int nt = 0; nt < 8; nt++) {
#pragma unroll
            for (int c = 0; c < 2; c++) {
                float p0 = __expf(s[nt][c] - mn0);
                s[nt][c] = p0; rs0 += p0;
                float p1 = __expf(s[nt][2 + c] - mn1);
                s[nt][2 + c] = p1; rs1 += p1;
            }
        }
        rs0 += __shfl_xor_sync(0xffffffffu, rs0, 1);
        rs0 += __shfl_xor_sync(0xffffffffu, rs0, 2);
        rs1 += __shfl_xor_sync(0xffffffffu, rs1, 1);
        rs1 += __shfl_xor_sync(0xffffffffu, rs1, 2);
        m0 = mn0; m1 = mn1;
        l0s = l0s * al0f + rs0;
        l1s = l1s * al1f + rs1;
#pragma unroll
        for (int nt = 0; nt < 8; nt++) {
            o[nt][0] *= al0f; o[nt][1] *= al0f;
            o[nt][2] *= al1f; o[nt][3] *= al1f;
        }

        // ---- drain V[kb] (overlapped by QK+softmax), then PV ----
        if (kb + 1 < kbEnd) CPA_WAIT(1);   // leaves K[kb+1] outstanding
        else                CPA_WAIT(0);
        __syncthreads();

#pragma unroll
        for (int ks = 0; ks < 4; ks++) {
            uint32_t ah0, al0, ah1, al1, ah2, al2, ah3, al3;
            bf16_split2(s[2 * ks][0],     s[2 * ks][1],     ah0, al0);
            bf16_split2(s[2 * ks][2],     s[2 * ks][3],     ah1, al1);
            bf16_split2(s[2 * ks + 1][0], s[2 * ks + 1][1], ah2, al2);
            bf16_split2(s[2 * ks + 1][2], s[2 * ks + 1][3], ah3, al3);
#pragma unroll
            for (int nt = 0; nt < 8; nt++) {
                uint4 vv = sV[(nt * 8 + gid) * 20 + ks * 4 + tig];
                mma_bf16(o[nt], ah0, ah1, ah2, ah3, vv.x, vv.y);
                mma_bf16(o[nt], ah0, ah1, ah2, ah3, vv.z, vv.w);
                mma_bf16(o[nt], al0, al1, al2, al3, vv.x, vv.y);
            }
        }
        __syncthreads();   // all warps done reading V before refill

        if (kb + 1 < kbEnd) {   // V[kb+1]: overlaps next iteration's QK+softmax
            const uint4* gv = vbase + (size_t)fj * 512 + (kb + 1) * 16 + fq;
            uint32_t dv = smb + (4608 + fj * 20 + fq) * 16;
#pragma unroll
            for (int c = 0; c < 4; c++) cpa16(dv + c * 16, gv + c);
            CPA_COMMIT();
        }
    }

    // ---- epilogue: merged interleaved positions (for O-gemm uint4 frags) ----
    float inv0 = (l0s > 0.f) ? 1.f / l0s : 0.f;
    float inv1 = (l1s > 0.f) ? 1.f / l1s : 0.f;
    size_t base0 = (size_t)(b * SS + i0) * 1024 + h * 64;
    size_t base1 = (size_t)(b * SS + i1) * 1024 + h * 64;
#pragma unroll
    for (int nt = 0; nt < 8; nt++) {
        int pos = (nt >> 1) * 16 + tig * 4 + (nt & 1);
        uint32_t h0, l0, h1, l1;
        bf16_split2(o[nt][0] * inv0, o[nt][1] * inv0, h0, l0);
        bf16_split2(o[nt][2] * inv1, o[nt][3] * inv1, h1, l1);
        go[base0 + pos] = h0; go[base0 + pos + 2] = l0;
        go[base1 + pos] = h1; go[base1 + pos + 2] = l1;
    }
}

// ---------------- gate: LN + dot(wg) + sigmoid (shfl reductions) -------------
__global__ void gate_kernel(const float* __restrict__ x,
                            const float* __restrict__ wg,
                            const float* __restrict__ bg,
                            const float* __restrict__ gamma,
                            const float* __restrict__ beta,
                            float* __restrict__ gates) {
    int token = blockIdx.x;
    const float* row = x + (size_t)token * HH;
    __shared__ float sm8[3][8];
    int tid = threadIdx.x, lane = tid & 31, wid = tid >> 5;

    float xr[4];
#pragma unroll
    for (int i = 0; i < 4; i++) xr[i] = row[tid + i * 256];

    float s = xr[0] + xr[1] + xr[2] + xr[3];
#pragma unroll
    for (int off = 16; off > 0; off >>= 1) s += __shfl_xor_sync(0xffffffffu, s, off);
    if (lane == 0) sm8[0][wid] = s;
    __syncthreads();
    float mu = 0.f;
#pragma unroll
    for (int i = 0; i < 8; i++) mu += sm8[0][i];
    mu *= (1.0f / HH);

    float v = 0.f;
#pragma unroll
    for (int i = 0; i < 4; i++) { float d = xr[i] - mu; v = fmaf(d, d, v); }
#pragma unroll
    for (int off = 16; off > 0; off >>= 1) v += __shfl_xor_sync(0xffffffffu, v, off);
    if (lane == 0) sm8[1][wid] = v;
    __syncthreads();
    float var = 0.f;
#pragma unroll
    for (int i = 0; i < 8; i++) var += sm8[1][i];
    float rstd = rsqrtf(var * (1.0f / HH) + 1e-5f);

    float dot = 0.f;
#pragma unroll
    for (int i = 0; i < 4; i++) {
        int hh = tid + i * 256;
        float y = fmaf((xr[i] - mu) * rstd, gamma[hh], beta[hh]);
        dot = fmaf(y, wg[hh], dot);
    }
#pragma unroll
    for (int off = 16; off > 0; off >>= 1) dot += __shfl_xor_sync(0xffffffffu, dot, off);
    if (lane == 0) sm8[2][wid] = dot;
    __syncthreads();
    if (tid == 0) {
        float z = sm8[2][0] + sm8[2][1] + sm8[2][2] + sm8[2][3]
                + sm8[2][4] + sm8[2][5] + sm8[2][6] + sm8[2][7] + bg[0];
        z = fminf(10.f, fmaxf(-10.f, z));
        gates[token] = 1.f / (1.f + expf(-z));
    }
}

// ---------------- gate regularization loss ------------------------------------
__global__ void regloss_kernel(const float* __restrict__ gates, float* __restrict__ out,
                               int writeIdx) {
    __shared__ float red[256];
    int tid = threadIdx.x;
    float acc = 0.f;
    for (int t = tid; t < MM; t += 256) {
        float g = gates[t];
        float gs = fminf(fmaxf(g, 1e-5f), 1.f - 1e-5f);
        float binary = g * (1.f - g);
        float ent = g * logf(gs) + (1.f - g) * logf(1.f - gs);
        acc += 0.1f * binary - 0.01f * ent + 0.1f * g;
    }
    red[tid] = acc; __syncthreads();
    for (int o = 128; o > 0; o >>= 1) { if (tid < o) red[tid] += red[tid + o]; __syncthreads(); }
    if (tid == 0) out[writeIdx] = red[0] * (1.0f / MM);
}

// ---------------- launch ------------------------------------------------------
extern "C" void kernel_launch(void* const* d_in, const int* in_sizes, int n_in,
                              void* d_out, int out_size) {
    const float* x     = (const float*)d_in[0];
    const float* Wq    = (const float*)d_in[1];
    const float* Wk    = (const float*)d_in[2];
    const float* Wv    = (const float*)d_in[3];
    const float* Wo    = (const float*)d_in[4];
    const float* Wg    = (const float*)d_in[5];
    const float* bg    = (const float*)d_in[6];
    const float* gamma = (const float*)d_in[7];
    const float* beta  = (const float*)d_in[8];
    float* out = (float*)d_out;

    float *pGates;
    uint32_t *pX, *pWq, *pWk, *pWv, *pWo;
    uint32_t *pQh, *pQl, *pKp, *pO;
    uint4 *pVp;
    int *pOrder;
    cudaGetSymbolAddress((void**)&pGates, g_gates);
    cudaGetSymbolAddress((void**)&pOrder, g_order);
    cudaGetSymbolAddress((void**)&pX,     g_x);
    cudaGetSymbolAddress((void**)&pWq,    g_wq);
    cudaGetSymbolAddress((void**)&pWk,    g_wk);
    cudaGetSymbolAddress((void**)&pWv,    g_wv);
    cudaGetSymbolAddress((void**)&pWo,    g_wo);
    cudaGetSymbolAddress((void**)&pQh,    g_qph);
    cudaGetSymbolAddress((void**)&pQl,    g_qpl);
    cudaGetSymbolAddress((void**)&pKp,    g_kp);
    cudaGetSymbolAddress((void**)&pVp,    g_vp);
    cudaGetSymbolAddress((void**)&pO,     g_o);

    cudaFuncSetAttribute(gemm_qkv, cudaFuncAttributeMaxDynamicSharedMemorySize, GM_SMEM);
    cudaFuncSetAttribute(gemm_mma, cudaFuncAttributeMaxDynamicSharedMemorySize, GM_SMEM);
    cudaFuncSetAttribute(attn_mma, cudaFuncAttributeMaxDynamicSharedMemorySize, AT_SMEM);

    gate_kernel<<<MM, 256>>>(x, Wg, bg, gamma, beta, pGates);
    build_order<<<BB, 256>>>(pGates, pOrder);

    split_all<<<1024, 256>>>(x, Wq, Wk, Wv, Wo, pX, pWq, pWk, pWv, pWo);

    gemm_qkv<<<384, 256, GM_SMEM>>>(pX, pWq, pWk, pWv, pQh, pQl, pKp, pVp);

    attn_mma<<<dim3(SS / 128, NHD, BB), 256, AT_SMEM>>>(
        pQh, pQl, (const uint4*)pKp, pVp, pGates, pOrder, pO);

    gemm_mma<<<dim3(HH / 128, MM / 128), 256, GM_SMEM>>>(
        pO, pWo, out, nullptr, nullptr, HH, KW, 0);

    if (out_size > MM * HH)
        regloss_kernel<<<1, 256>>>(pGates, out, MM * HH);
}

// round 17
// speedup vs baseline: 1.0335x; 1.0335x over previous
#include <cuda_runtime.h>
#include <cuda_bf16.h>
#include <math.h>
#include <stdint.h>

// Problem constants
#define BB  2
#define SS  2048
#define HH  1024
#define NHD 16      // num heads
#define HDD 64      // head dim
#define RHH 4       // kv heads
#define MM  (BB*SS) // 4096 token rows
#define KW  (HH/2)  // 512 hi-words per row (bf16x2); merged row = 2*KW words

// word counts per tensor (hi-words, for merged split kernel)
#define XW  (MM*KW)
#define WQW (HH*KW)
#define WKW ((RHH*HDD)*KW)
#define TOTW (XW + WQW + 2*WKW + WQW)

// ---------------- scratch (static device memory; no allocs allowed) ----------
__device__ float    g_gates[MM];
__device__ int      g_order[MM];
__device__ uint32_t g_x [(size_t)MM * 2 * KW];          // x merged hi/lo interleaved
__device__ uint32_t g_wq[(size_t)HH * 2 * KW];
__device__ uint32_t g_wk[(size_t)(RHH*HDD) * 2 * KW];
__device__ uint32_t g_wv[(size_t)(RHH*HDD) * 2 * KW];
__device__ uint32_t g_wo[(size_t)HH * 2 * KW];
__device__ uint32_t g_qph[(size_t)MM * 512];            // Q row-packed bf16 hi (raw order)
__device__ uint32_t g_qpl[(size_t)MM * 512];
__device__ uint32_t g_kp [(size_t)RHH * MM * 64];       // K frag-packed (hi+lo interleaved u4)
__device__ uint4    g_vp [(size_t)BB * RHH * HDD * 512];// V transposed frag-packed
__device__ uint32_t g_o  [(size_t)MM * 1024];           // attn out merged hi/lo interleaved

// ---------------- bf16 helpers ----------------------------------------------
__device__ __forceinline__ uint32_t pack_bf16(float lowElem, float highElem) {
    uint32_t r;
    asm("cvt.rn.bf16x2.f32 %0, %1, %2;" : "=r"(r) : "f"(highElem), "f"(lowElem));
    return r;
}
__device__ __forceinline__ float bf16_round(float x) {
    return __bfloat162float(__float2bfloat16(x));
}
__device__ __forceinline__ void bf16_split2(float a, float b, uint32_t& hi, uint32_t& lo) {
    hi = pack_bf16(a, b);
    lo = pack_bf16(a - bf16_round(a), b - bf16_round(b));
}
__device__ __forceinline__ void mma_bf16(float* c, uint32_t a0, uint32_t a1, uint32_t a2,
                                         uint32_t a3, uint32_t b0, uint32_t b1) {
    asm volatile(
        "mma.sync.aligned.m16n8k16.row.col.f32.bf16.bf16.f32 "
        "{%0,%1,%2,%3}, {%4,%5,%6,%7}, {%8,%9}, {%0,%1,%2,%3};"
        : "+f"(c[0]), "+f"(c[1]), "+f"(c[2]), "+f"(c[3])
        : "r"(a0), "r"(a1), "r"(a2), "r"(a3), "r"(b0), "r"(b1));
}
__device__ __forceinline__ uint32_t smem_u32(const void* p) {
    uint32_t a;
    asm("{ .reg .u64 t; cvta.to.shared.u64 t, %1; cvt.u32.u64 %0, t; }" : "=r"(a) : "l"(p));
    return a;
}
__device__ __forceinline__ void cpa16(uint32_t dst, const void* src) {
    asm volatile("cp.async.ca.shared.global [%0], [%1], 16;" :: "r"(dst), "l"(src));
}
#define CPA_COMMIT() asm volatile("cp.async.commit_group;" ::: "memory")
#define CPA_WAIT(n)  asm volatile("cp.async.wait_group %0;" :: "n"(n) : "memory")

// ---------------- merged fp32 -> interleaved hi/lo split ---------------------
__global__ __launch_bounds__(256)
void split_all(const float* __restrict__ x,  const float* __restrict__ Wq,
               const float* __restrict__ Wk, const float* __restrict__ Wv,
               const float* __restrict__ Wo,
               uint32_t* __restrict__ xo,  uint32_t* __restrict__ wqo,
               uint32_t* __restrict__ wko, uint32_t* __restrict__ wvo,
               uint32_t* __restrict__ woo) {
    for (int i = blockIdx.x * 256 + threadIdx.x; i < TOTW; i += gridDim.x * 256) {
        const float* src; uint32_t* dst; int local;
        if (i < XW)                      { src = x;  dst = xo;  local = i; }
        else if (i < XW + WQW)           { src = Wq; dst = wqo; local = i - XW; }
        else if (i < XW + WQW + WKW)     { src = Wk; dst = wko; local = i - XW - WQW; }
        else if (i < XW + WQW + 2*WKW)   { src = Wv; dst = wvo; local = i - XW - WQW - WKW; }
        else                             { src = Wo; dst = woo; local = i - XW - WQW - 2*WKW; }
        float2 v = *(const float2*)(src + 2 * (size_t)local);
        uint32_t h, l;
        bf16_split2(v.x, v.y, h, l);
        int t = local & 7;
        size_t pos = ((size_t)(local >> 3)) * 16 + (t & 3) * 4 + (t >> 2);
        dst[pos] = h; dst[pos + 2] = l;
    }
}

// ==================== tensor-core bf16x3 GEMM (merged interleaved) ===========
#define PWG 48
#define STGW (2 * 128 * PWG)
#define GM_SMEM (2 * STGW * 4)

__device__ __forceinline__ void gemm_body(const uint32_t* __restrict__ A,
                                          const uint32_t* __restrict__ B,
                                          float* __restrict__ C,
                                          uint32_t* __restrict__ outh,
                                          uint32_t* __restrict__ outl,
                                          uint4* __restrict__ vpout,
                                          int N, int Kw, int mode,
                                          int rowBase, int colBase, uint32_t* sm) {
    int tid = threadIdx.x, lane = tid & 31, wid = tid >> 5;
    int gid = lane >> 2, tig = lane & 3;
    int wM = wid >> 1, wN = wid & 1;
    uint32_t smb = smem_u32(sm);

    int lrow = tid >> 1, lh16 = (tid & 1) * 16;
    const uint32_t* pA = A + (size_t)(rowBase + lrow) * (2 * Kw) + lh16;
    const uint32_t* pB = B + (size_t)(colBase + lrow) * (2 * Kw) + lh16;
    uint32_t dstOff = (lrow * PWG + lh16) * 4;

    float acc[2][8][4];
#pragma unroll
    for (int mt = 0; mt < 2; mt++)
#pragma unroll
        for (int nt = 0; nt < 8; nt++)
#pragma unroll
            for (int c = 0; c < 4; c++) acc[mt][nt][c] = 0.f;

    const int NST = Kw / 16;

    {
        uint32_t dA = smb + dstOff;
        uint32_t dB = dA + 128 * PWG * 4;
#pragma unroll
        for (int c = 0; c < 4; c++) { cpa16(dA + c * 16, pA + c * 4); cpa16(dB + c * 16, pB + c * 4); }
        CPA_COMMIT();
    }

    for (int s = 0; s < NST; s++) {
        int buf = s & 1;
        if (s + 1 < NST) {
            int off = (s + 1) * 32;
            uint32_t dA = smb + (buf ^ 1) * STGW * 4 + dstOff;
            uint32_t dB = dA + 128 * PWG * 4;
#pragma unroll
            for (int c = 0; c < 4; c++) {
                cpa16(dA + c * 16, pA + off + c * 4);
                cpa16(dB + c * 16, pB + off + c * 4);
            }
            CPA_COMMIT();
            CPA_WAIT(1);
        } else {
            CPA_WAIT(0);
        }
        __syncthreads();

        uint32_t* sA = sm + buf * STGW;
        uint32_t* sB = sA + 128 * PWG;

#pragma unroll
        for (int ks = 0; ks < 2; ks++) {
            uint32_t ah[2][4], al[2][4];
#pragma unroll
            for (int mt = 0; mt < 2; mt++) {
                int r0 = (wM * 32 + mt * 16 + gid) * PWG + ks * 16 + tig * 4;
                uint4 q1 = *(const uint4*)(sA + r0);
                uint4 q2 = *(const uint4*)(sA + r0 + 8 * PWG);
                ah[mt][0] = q1.x; ah[mt][1] = q2.x; ah[mt][2] = q1.y; ah[mt][3] = q2.y;
                al[mt][0] = q1.z; al[mt][1] = q2.z; al[mt][2] = q1.w; al[mt][3] = q2.w;
            }
#pragma unroll
            for (int nt = 0; nt < 8; nt++) {
                int n0 = (wN * 64 + nt * 8 + gid) * PWG + ks * 16 + tig * 4;
                uint4 qb = *(const uint4*)(sB + n0);
#pragma unroll
                for (int mt = 0; mt < 2; mt++) {
                    mma_bf16(acc[mt][nt], ah[mt][0], ah[mt][1], ah[mt][2], ah[mt][3], qb.x, qb.y);
                    mma_bf16(acc[mt][nt], ah[mt][0], ah[mt][1], ah[mt][2], ah[mt][3], qb.z, qb.w);
                    mma_bf16(acc[mt][nt], al[mt][0], al[mt][1], al[mt][2], al[mt][3], qb.x, qb.y);
                }
            }
        }
        __syncthreads();
    }

    // ---------------- epilogue ----------------
    if (mode == 0) {
#pragma unroll
        for (int mt = 0; mt < 2; mt++) {
            int r0 = rowBase + wM * 32 + mt * 16 + gid;
#pragma unroll
            for (int nt = 0; nt < 8; nt++) {
                int c0 = colBase + wN * 64 + nt * 8 + 2 * tig;
                *(float2*)(C + (size_t)r0 * N + c0) = make_float2(acc[mt][nt][0], acc[mt][nt][1]);
                *(float2*)(C + (size_t)(r0 + 8) * N + c0) = make_float2(acc[mt][nt][2], acc[mt][nt][3]);
            }
        }
    } else if (mode == 1) {   // Q row-packed raw order, scaled 1/8
#pragma unroll
        for (int mt = 0; mt < 2; mt++) {
            int r0 = rowBase + wM * 32 + mt * 16 + gid;
#pragma unroll
            for (int nt = 0; nt < 8; nt++) {
                int c0 = colBase + wN * 64 + nt * 8 + 2 * tig;
                int hh = c0 >> 6, w32 = (c0 & 63) >> 1;
                uint32_t h0, l0, h1, l1;
                bf16_split2(acc[mt][nt][0] * 0.125f, acc[mt][nt][1] * 0.125f, h0, l0);
                bf16_split2(acc[mt][nt][2] * 0.125f, acc[mt][nt][3] * 0.125f, h1, l1);
                size_t i0 = ((size_t)r0 * 16 + hh) * 32 + w32;
                size_t i1 = ((size_t)(r0 + 8) * 16 + hh) * 32 + w32;
                outh[i0] = h0; outl[i0] = l0;
                outh[i1] = h1; outl[i1] = l1;
            }
        }
    } else if (mode == 2) {   // K frag-packed interleaved
#pragma unroll
        for (int mt = 0; mt < 2; mt++) {
            int r0 = rowBase + wM * 32 + mt * 16 + gid;
#pragma unroll
            for (int nt = 0; nt < 8; nt++) {
                int c0 = colBase + wN * 64 + nt * 8 + 2 * tig;
                int kvh = c0 >> 6, wl = (c0 & 63) >> 1;
                int ks = wl >> 3, tigg = wl & 7;
                int tA = tigg & 3, comp = (tigg & 4) ? 1 : 0;
                size_t wi0 = (((size_t)kvh * MM + r0) * 16 + ks * 4 + tA) * 4;
                size_t wi1 = wi0 + 8 * 16 * 4;
                uint32_t h0, l0, h1, l1;
                bf16_split2(acc[mt][nt][0], acc[mt][nt][1], h0, l0);
                bf16_split2(acc[mt][nt][2], acc[mt][nt][3], h1, l1);
                outh[wi0 + comp] = h0; outh[wi0 + comp + 2] = l0;
                outh[wi1 + comp] = h1; outh[wi1 + comp + 2] = l1;
            }
        }
    } else {                  // mode 3: V transposed frag-packed (shfl pair exchange)
#pragma unroll
        for (int mt = 0; mt < 2; mt++) {
            int r = wM * 32 + mt * 16 + gid;
            int tok = rowBase + r;
            int b = tok / SS;
            int j64 = tok % SS;
            int kb = j64 >> 6;
            int j = j64 & 63;
            int ks = j >> 4, tg = (j >> 1) & 3;
            bool even = (gid & 1) == 0;
#pragma unroll
            for (int nt = 0; nt < 8; nt++) {
                int c0 = colBase + wN * 64 + nt * 8 + 2 * tig;
                float p0 = __shfl_xor_sync(0xffffffffu, acc[mt][nt][0], 4);
                float p1 = __shfl_xor_sync(0xffffffffu, acc[mt][nt][1], 4);
                float p2 = __shfl_xor_sync(0xffffffffu, acc[mt][nt][2], 4);
                float p3 = __shfl_xor_sync(0xffffffffu, acc[mt][nt][3], 4);
                float v0, v1, v2, v3; int d;
                if (even) { d = c0;     v0 = acc[mt][nt][0]; v1 = p0; v2 = acc[mt][nt][2]; v3 = p2; }
                else      { d = c0 + 1; v0 = p1; v1 = acc[mt][nt][1]; v2 = p3; v3 = acc[mt][nt][3]; }
                int kvh = d >> 6, dd = d & 63;
                uint32_t hx, lx, hy, ly;
                bf16_split2(v0, v1, hx, lx);
                bf16_split2(v2, v3, hy, ly);
                vpout[((size_t)(b * RHH + kvh) * 64 + dd) * 512 + kb * 16 + ks * 4 + tg] =
                    make_uint4(hx, hy, lx, ly);
            }
        }
    }
}

// fused Q+K+V projection in one launch (wave packing)
__global__ __launch_bounds__(256, 2)
void gemm_qkv(const uint32_t* __restrict__ xm,  const uint32_t* __restrict__ wqm,
              const uint32_t* __restrict__ wkm, const uint32_t* __restrict__ wvm,
              uint32_t* __restrict__ qh, uint32_t* __restrict__ ql,
              uint32_t* __restrict__ kp, uint4* __restrict__ vpout) {
    extern __shared__ uint32_t smg[];
    int bx = blockIdx.x;
    if (bx < 256) {
        gemm_body(xm, wqm, nullptr, qh, ql, nullptr, HH, KW, 1,
                  (bx >> 3) * 128, (bx & 7) * 128, smg);
    } else if (bx < 320) {
        int c = bx - 256;
        gemm_body(xm, wkm, nullptr, kp, nullptr, nullptr, RHH * HDD, KW, 2,
                  (c >> 1) * 128, (c & 1) * 128, smg);
    } else {
        int c = bx - 320;
        gemm_body(xm, wvm, nullptr, nullptr, nullptr, vpout, RHH * HDD, KW, 3,
                  (c >> 1) * 128, (c & 1) * 128, smg);
    }
}

__global__ __launch_bounds__(256, 2)
void gemm_mma(const uint32_t* __restrict__ A, const uint32_t* __restrict__ B,
              float* __restrict__ C, uint32_t* __restrict__ outh,
              uint32_t* __restrict__ outl, int N, int Kw, int mode) {
    extern __shared__ uint32_t smg[];
    gemm_body(A, B, C, outh, outl, nullptr, N, Kw, mode,
              blockIdx.y * 128, blockIdx.x * 128, smg);
}

// ---------------- build compacted row order: [causal asc | local asc] --------
__global__ __launch_bounds__(256)
void build_order(const float* __restrict__ gates, int* __restrict__ order) {
    int b = blockIdx.x, tid = threadIdx.x;
    __shared__ int cnt[256];
    bool loc[8];
    int c = 0;
#pragma unroll
    for (int i = 0; i < 8; i++) {
        loc[i] = gates[b * SS + tid * 8 + i] <= 0.5f;
        if (!loc[i]) c++;
    }
    cnt[tid] = c;
    __syncthreads();
    for (int off = 1; off < 256; off <<= 1) {
        int add = (tid >= off) ? cnt[tid - off] : 0;
        __syncthreads();
        cnt[tid] += add;
        __syncthreads();
    }
    int nC = cnt[255];
    int cb = cnt[tid] - c;
    int lb = nC + (tid * 8 - cb);
#pragma unroll
    for (int i = 0; i < 8; i++) {
        if (loc[i]) order[b * SS + lb++] = tid * 8 + i;
        else        order[b * SS + cb++] = tid * 8 + i;
    }
}

// ==================== mma flash attention (compacted rows) ===================
// Q pitch padded to 20 u4 (conflict-free LDS.128, matches K/V pitch).
// SMEM (uint4): Q hi [0,1280) lo [1280,2560); K buf{0,1} @2560+buf*1280; V @5120.
#define AT_SMEM (6400 * 16)

__global__ __launch_bounds__(256, 2)
void attn_mma(const uint32_t* __restrict__ qph, const uint32_t* __restrict__ qpl,
              const uint4* __restrict__ kp,  const uint4* __restrict__ vp,
              const float* __restrict__ gates, const int* __restrict__ order,
              uint32_t* __restrict__ go) {
    extern __shared__ uint4 sm4[];
    __shared__ int srows[128];
    __shared__ int sminlo, smaxhi;
    uint32_t smb = smem_u32(sm4);
    uint32_t* sQw = (uint32_t*)sm4;

    int bx = blockIdx.x;
    int t = (bx < 8) ? (7 - bx) : bx;   // longest (causal) tiles first
    int h = blockIdx.y, b = blockIdx.z;
    int tid = threadIdx.x, lane = tid & 31, w = tid >> 5;
    int gid = lane >> 2, tig = lane & 3;
    int kvh = h & 3;

    if (tid == 0) { sminlo = SS; smaxhi = 0; }
    if (tid < 128) srows[tid] = order[b * SS + t * 128 + tid];
    __syncthreads();
    if (tid < 128) {
        int myi = srows[tid];
        bool isl = gates[b * SS + myi] <= 0.5f;
        int lo = isl ? max(0, myi - 64) : 0;
        int hi = isl ? min(SS - 1, myi + 64) : myi;
        atomicMin(&sminlo, lo);
        atomicMax(&smaxhi, hi);
    }

    // ---- Q gather: row-major packed (raw order) -> frag layout, pitch 20 u4 ----
    {
        int r = tid >> 1, half = tid & 1;
        int ri = srows[r];
        const uint32_t* src = (half ? qpl : qph) + ((size_t)(b * SS + ri) * 16 + h) * 32;
        uint32_t* dst = sQw + half * 5120;   // 1280 u4 = 5120 words per half
        int wd = r >> 4, g2 = r & 15;
        int gidq = g2 & 7, hiRow = g2 >> 3;
#pragma unroll
        for (int w32 = 0; w32 < 32; w32++) {
            int ks = w32 >> 3, rem = w32 & 7;
            int tg2 = rem & 3, comp = ((rem >> 2) << 1) | hiRow;
            dst[((wd * 8 + gidq) * 20 + ks * 4 + tg2) * 4 + comp] = src[w32];
        }
    }
    __syncthreads();

    int kbStart = sminlo >> 6;
    int kbEnd = (smaxhi >> 6) + 1;

    int i0 = srows[w * 16 + gid], i1 = srows[w * 16 + gid + 8];
    bool isl0 = gates[b * SS + i0] <= 0.5f;
    bool isl1 = gates[b * SS + i1] <= 0.5f;

    float m0 = -1e30f, m1 = -1e30f, l0s = 0.f, l1s = 0.f;
    float o[8][4];
#pragma unroll
    for (int nt = 0; nt < 8; nt++)
#pragma unroll
        for (int c = 0; c < 4; c++) o[nt][c] = 0.f;

    const uint4* kbase = kp + ((size_t)kvh * MM + b * SS) * 16;
    const uint4* vbase = vp + (size_t)(b * RHH + kvh) * 64 * 512;
    int fj = tid >> 2, fq = (tid & 3) * 4;

    {
        const uint4* gk = kbase + ((size_t)(kbStart * 64 + fj)) * 16 + fq;
        const uint4* gv = vbase + (size_t)fj * 512 + kbStart * 16 + fq;
        uint32_t dk = smb + (2560 + fj * 20 + fq) * 16;
        uint32_t dv = smb + (5120 + fj * 20 + fq) * 16;
#pragma unroll
        for (int c = 0; c < 4; c++) { cpa16(dk + c * 16, gk + c); cpa16(dv + c * 16, gv + c); }
        CPA_COMMIT();
    }

    for (int kb = kbStart; kb < kbEnd; kb++) {
        int buf = (kb - kbStart) & 1;
        CPA_WAIT(0);
        __syncthreads();

        if (kb + 1 < kbEnd) {
            const uint4* gk = kbase + ((size_t)((kb + 1) * 64 + fj)) * 16 + fq;
            uint32_t dk = smb + (2560 + (buf ^ 1) * 1280 + fj * 20 + fq) * 16;
#pragma unroll
            for (int c = 0; c < 4; c++) cpa16(dk + c * 16, gk + c);
            CPA_COMMIT();
        }

        const uint4* sK = sm4 + 2560 + buf * 1280;
        const uint4* sV = sm4 + 5120;

        // ---- QK^T ----
        float s[8][4];
#pragma unroll
        for (int nt = 0; nt < 8; nt++)
#pragma unroll
            for (int c = 0; c < 4; c++) s[nt][c] = 0.f;

#pragma unroll
        for (int ks = 0; ks < 4; ks++) {
            uint4 qh = sm4[(w * 8 + gid) * 20 + ks * 4 + tig];
            uint4 ql = sm4[1280 + (w * 8 + gid) * 20 + ks * 4 + tig];
#pragma unroll
            for (int nt = 0; nt < 8; nt++) {
                uint4 kk = sK[(nt * 8 + gid) * 20 + ks * 4 + tig];
                mma_bf16(s[nt], qh.x, qh.y, qh.z, qh.w, kk.x, kk.y);
                mma_bf16(s[nt], qh.x, qh.y, qh.z, qh.w, kk.z, kk.w);
                mma_bf16(s[nt], ql.x, ql.y, ql.z, ql.w, kk.x, kk.y);
            }
        }

        // ---- mask + online softmax ----
        float rm0 = -1e30f, rm1 = -1e30f;
#pragma unroll
        for (int nt = 0; nt < 8; nt++) {
            int jb = kb * 64 + nt * 8 + 2 * tig;
#pragma unroll
            for (int c = 0; c < 2; c++) {
                int j = jb + c;
                bool v0 = isl0 ? (abs(i0 - j) <= 64) : (j <= i0);
                s[nt][c] = v0 ? s[nt][c] : -1e30f;
                rm0 = fmaxf(rm0, s[nt][c]);
                bool v1 = isl1 ? (abs(i1 - j) <= 64) : (j <= i1);
                s[nt][2 + c] = v1 ? s[nt][2 + c] : -1e30f;
                rm1 = fmaxf(rm1, s[nt][2 + c]);
            }
        }
        rm0 = fmaxf(rm0, __shfl_xor_sync(0xffffffffu, rm0, 1));
        rm0 = fmaxf(rm0, __shfl_xor_sync(0xffffffffu, rm0, 2));
        rm1 = fmaxf(rm1, __shfl_xor_sync(0xffffffffu, rm1, 1));
        rm1 = fmaxf(rm1, __shfl_xor_sync(0xffffffffu, rm1, 2));

        float mn0 = fmaxf(m0, rm0), mn1 = fmaxf(m1, rm1);
        float al0f = __expf(fmaxf(m0 - mn0, -80.f));
        float al1f = __expf(fmaxf(m1 - mn1, -80.f));
        float rs0 = 0.f, rs1 = 0.f;
#pragma unroll
        for (int nt = 0; nt < 8; nt++) {
#pragma unroll
            for (int c = 0; c < 2; c++) {
                float p0 = __expf(fmaxf(s[nt][c] - mn0, -80.f));
                s[nt][c] = p0; rs0 += p0;
                float p1 = __expf(fmaxf(s[nt][2 + c] - mn1, -80.f));
                s[nt][2 + c] = p1; rs1 += p1;
            }
        }
        rs0 += __shfl_xor_sync(0xffffffffu, rs0, 1);
        rs0 += __shfl_xor_sync(0xffffffffu, rs0, 2);
        rs1 += __shfl_xor_sync(0xffffffffu, rs1, 1);
        rs1 += __shfl_xor_sync(0xffffffffu, rs1, 2);
        m0 = mn0; m1 = mn1;
        l0s = l0s * al0f + rs0;
        l1s = l1s * al1f + rs1;
#pragma unroll
        for (int nt = 0; nt < 8; nt++) {
            o[nt][0] *= al0f; o[nt][1] *= al0f;
            o[nt][2] *= al1f; o[nt][3] *= al1f;
        }

        // ---- PV (P from registers, single V buffer) ----
#pragma unroll
        for (int ks = 0; ks < 4; ks++) {
            uint32_t ah0, al0, ah1, al1, ah2, al2, ah3, al3;
            bf16_split2(s[2 * ks][0],     s[2 * ks][1],     ah0, al0);
            bf16_split2(s[2 * ks][2],     s[2 * ks][3],     ah1, al1);
            bf16_split2(s[2 * ks + 1][0], s[2 * ks + 1][1], ah2, al2);
            bf16_split2(s[2 * ks + 1][2], s[2 * ks + 1][3], ah3, al3);
#pragma unroll
            for (int nt = 0; nt < 8; nt++) {
                uint4 vv = sV[(nt * 8 + gid) * 20 + ks * 4 + tig];
                mma_bf16(o[nt], ah0, ah1, ah2, ah3, vv.x, vv.y);
                mma_bf16(o[nt], ah0, ah1, ah2, ah3, vv.z, vv.w);
                mma_bf16(o[nt], al0, al1, al2, al3, vv.x, vv.y);
            }
        }
        __syncthreads();

        if (kb + 1 < kbEnd) {
            const uint4* gv = vbase + (size_t)fj * 512 + (kb + 1) * 16 + fq;
            uint32_t dv = smb + (5120 + fj * 20 + fq) * 16;
#pragma unroll
            for (int c = 0; c < 4; c++) cpa16(dv + c * 16, gv + c);
            CPA_COMMIT();
        }
    }

    // ---- epilogue: merged interleaved positions (for O-gemm uint4 frags) ----
    float inv0 = (l0s > 0.f) ? 1.f / l0s : 0.f;
    float inv1 = (l1s > 0.f) ? 1.f / l1s : 0.f;
    size_t base0 = (size_t)(b * SS + i0) * 1024 + h * 64;
    size_t base1 = (size_t)(b * SS + i1) * 1024 + h * 64;
#pragma unroll
    for (int nt = 0; nt < 8; nt++) {
        int pos = (nt >> 1) * 16 + tig * 4 + (nt & 1);
        uint32_t h0, l0, h1, l1;
        bf16_split2(o[nt][0] * inv0, o[nt][1] * inv0, h0, l0);
        bf16_split2(o[nt][2] * inv1, o[nt][3] * inv1, h1, l1);
        go[base0 + pos] = h0; go[base0 + pos + 2] = l0;
        go[base1 + pos] = h1; go[base1 + pos + 2] = l1;
    }
}

// ---------------- gate: LN + dot(wg) + sigmoid(clamp) -----------------------
__global__ void gate_kernel(const float* __restrict__ x,
                            const float* __restrict__ wg,
                            const float* __restrict__ bg,
                            const float* __restrict__ gamma,
                            const float* __restrict__ beta,
                            float* __restrict__ gates) {
    int token = blockIdx.x;
    const float* row = x + (size_t)token * HH;
    __shared__ float red[256];
    int tid = threadIdx.x;

    float xr[4];
#pragma unroll
    for (int i = 0; i < 4; i++) xr[i] = row[tid + i * 256];

    float s = xr[0] + xr[1] + xr[2] + xr[3];
    red[tid] = s; __syncthreads();
    for (int o = 128; o > 0; o >>= 1) { if (tid < o) red[tid] += red[tid + o]; __syncthreads(); }
    float mu = red[0] * (1.0f / HH);
    __syncthreads();

    float v = 0.f;
#pragma unroll
    for (int i = 0; i < 4; i++) { float d = xr[i] - mu; v = fmaf(d, d, v); }
    red[tid] = v; __syncthreads();
    for (int o = 128; o > 0; o >>= 1) { if (tid < o) red[tid] += red[tid + o]; __syncthreads(); }
    float rstd = rsqrtf(red[0] * (1.0f / HH) + 1e-5f);
    __syncthreads();

    float dot = 0.f;
#pragma unroll
    for (int i = 0; i < 4; i++) {
        int hh = tid + i * 256;
        float y = fmaf((xr[i] - mu) * rstd, gamma[hh], beta[hh]);
        dot = fmaf(y, wg[hh], dot);
    }
    red[tid] = dot; __syncthreads();
    for (int o = 128; o > 0; o >>= 1) { if (tid < o) red[tid] += red[tid + o]; __syncthreads(); }
    if (tid == 0) {
        float z = red[0] + bg[0];
        z = fminf(10.f, fmaxf(-10.f, z));
        gates[token] = 1.f / (1.f + expf(-z));
    }
}

// ---------------- gate regularization loss ------------------------------------
__global__ void regloss_kernel(const float* __restrict__ gates, float* __restrict__ out,
                               int writeIdx) {
    __shared__ float red[256];
    int tid = threadIdx.x;
    float acc = 0.f;
    for (int t = tid; t < MM; t += 256) {
        float g = gates[t];
        float gs = fminf(fmaxf(g, 1e-5f), 1.f - 1e-5f);
        float binary = g * (1.f - g);
        float ent = g * logf(gs) + (1.f - g) * logf(1.f - gs);
        acc += 0.1f * binary - 0.01f * ent + 0.1f * g;
    }
    red[tid] = acc; __syncthreads();
    for (int o = 128; o > 0; o >>= 1) { if (tid < o) red[tid] += red[tid + o]; __syncthreads(); }
    if (tid == 0) out[writeIdx] = red[0] * (1.0f / MM);
}

// ---------------- launch ------------------------------------------------------
extern "C" void kernel_launch(void* const* d_in, const int* in_sizes, int n_in,
                              void* d_out, int out_size) {
    const float* x     = (const float*)d_in[0];
    const float* Wq    = (const float*)d_in[1];
    const float* Wk    = (const float*)d_in[2];
    const float* Wv    = (const float*)d_in[3];
    const float* Wo    = (const float*)d_in[4];
    const float* Wg    = (const float*)d_in[5];
    const float* bg    = (const float*)d_in[6];
    const float* gamma = (const float*)d_in[7];
    const float* beta  = (const float*)d_in[8];
    float* out = (float*)d_out;

    float *pGates;
    uint32_t *pX, *pWq, *pWk, *pWv, *pWo;
    uint32_t *pQh, *pQl, *pKp, *pO;
    uint4 *pVp;
    int *pOrder;
    cudaGetSymbolAddress((void**)&pGates, g_gates);
    cudaGetSymbolAddress((void**)&pOrder, g_order);
    cudaGetSymbolAddress((void**)&pX,     g_x);
    cudaGetSymbolAddress((void**)&pWq,    g_wq);
    cudaGetSymbolAddress((void**)&pWk,    g_wk);
    cudaGetSymbolAddress((void**)&pWv,    g_wv);
    cudaGetSymbolAddress((void**)&pWo,    g_wo);
    cudaGetSymbolAddress((void**)&pQh,    g_qph);
    cudaGetSymbolAddress((void**)&pQl,    g_qpl);
    cudaGetSymbolAddress((void**)&pKp,    g_kp);
    cudaGetSymbolAddress((void**)&pVp,    g_vp);
    cudaGetSymbolAddress((void**)&pO,     g_o);

    cudaFuncSetAttribute(gemm_qkv, cudaFuncAttributeMaxDynamicSharedMemorySize, GM_SMEM);
    cudaFuncSetAttribute(gemm_mma, cudaFuncAttributeMaxDynamicSharedMemorySize, GM_SMEM);
    cudaFuncSetAttribute(attn_mma, cudaFuncAttributeMaxDynamicSharedMemorySize, AT_SMEM);

    gate_kernel<<<MM, 256>>>(x, Wg, bg, gamma, beta, pGates);
    build_order<<<BB, 256>>>(pGates, pOrder);

    split_all<<<1024, 256>>>(x, Wq, Wk, Wv, Wo, pX, pWq, pWk, pWv, pWo);

    gemm_qkv<<<384, 256, GM_SMEM>>>(pX, pWq, pWk, pWv, pQh, pQl, pKp, pVp);

    attn_mma<<<dim3(SS / 128, NHD, BB), 256, AT_SMEM>>>(
        pQh, pQl, (const uint4*)pKp, pVp, pGates, pOrder, pO);

    gemm_mma<<<dim3(HH / 128, MM / 128), 256, GM_SMEM>>>(
        pO, pWo, out, nullptr, nullptr, HH, KW, 0);

    if (out_size > MM * HH)
        regloss_kernel<<<1, 256>>>(pGates, out, MM * HH);
}